// round 4
// baseline (speedup 1.0000x reference)
#include <cuda_runtime.h>

// Mandelbrot boundary-proximity loss, two-phase + analytic in-set filter.
// R4: phase 1 is fully branchless (sticky escape predicate, predicated
// iteration counter) -> no BRA/BSSY/BSYNC in the hot unrolled loop.
//
// Semantics: non-escaping-within-100 points end at iters=100 (cycle detect
// or exhaustion). Cardioid/period-2-bulb points provably never escape =>
// dist=70 with zero iteration work. Escape arithmetic is source-identical
// to the validated R1 kernel, so the classification boundary is unchanged.
//
// Reduction: exact integer sum (ULL atomics) => deterministic.

#define MAX_ITERS 100
#define K1 12
#define NMAX 8388608
#define P1_THREADS 512
#define P2_BLOCKS 2048
#define P2_THREADS 256

__device__ unsigned long long g_sum;      // zero-init at load
__device__ unsigned int g_nsurv;          // zero-init at load
__device__ unsigned int g_surv[NMAX];

// ---------------------------------------------------------------- phase 1
__global__ void __launch_bounds__(P1_THREADS) phase1_kernel(
    const float* __restrict__ c_real,
    const float* __restrict__ c_imag,
    int n)
{
    const int idx  = blockIdx.x * P1_THREADS + threadIdx.x;
    const int lane = threadIdx.x & 31;
    const int wid  = threadIdx.x >> 5;

    unsigned int dist = 0;
    bool surv = false;

    if (idx < n) {
        const float cr = c_real[idx];
        const float ci = c_imag[idx];

        // analytic in-set tests (main cardioid + period-2 bulb)
        const float ci2 = ci * ci;
        const float xm  = cr - 0.25f;
        const float q   = xm * xm + ci2;
        const float xp  = cr + 1.0f;
        const bool in_set = (q * (q + xm) < 0.25f * ci2) |
                            (xp * xp + ci2 < 0.0625f);

        if (in_set) {
            dist = 70u;                        // iters = 100 exactly
        } else {
            // branchless 12-step escape probe
            float zr = 0.0f, zi = 0.0f;
            bool esc = false;
            int cnt = 0;

            #pragma unroll
            for (int i = 0; i < K1; ++i) {
                float zr2 = zr * zr - zi * zi + cr;        // same expr as R1
                float zi2 = fmaf(2.0f * zr, zi, ci);
                float mag = fmaf(zr2, zr2, zi2 * zi2);
                esc |= (mag > 4.0f);           // sticky: NaN-after-escape safe
                cnt += esc ? 0 : 1;            // predicated IADD
                zr = zr2; zi = zi2;
            }

            if (esc) dist = (unsigned int)(29 - cnt);  // iters = cnt+1 <= 12
            else     surv = true;
        }
    }

    // ---- block-aggregated survivor append ----
    __shared__ unsigned int warp_cnt[P1_THREADS / 32];
    __shared__ unsigned int block_base;

    const unsigned int mask = __ballot_sync(0xFFFFFFFFu, surv);
    if (lane == 0) warp_cnt[wid] = (unsigned int)__popc(mask);
    __syncthreads();

    if (threadIdx.x == 0) {
        unsigned int tot = 0;
        #pragma unroll
        for (int w = 0; w < P1_THREADS / 32; ++w) {
            unsigned int c = warp_cnt[w];
            warp_cnt[w] = tot;
            tot += c;
        }
        block_base = tot ? atomicAdd(&g_nsurv, tot) : 0u;
    }
    __syncthreads();

    if (surv) {
        unsigned int pos = block_base + warp_cnt[wid]
                         + (unsigned int)__popc(mask & ((1u << lane) - 1u));
        g_surv[pos] = (unsigned int)idx;
    }

    // ---- exact-integer distance reduction ----
    #pragma unroll
    for (int off = 16; off > 0; off >>= 1)
        dist += __shfl_down_sync(0xFFFFFFFFu, dist, off);

    __shared__ unsigned int warp_sums[P1_THREADS / 32];
    if (lane == 0) warp_sums[wid] = dist;
    __syncthreads();

    if (wid == 0) {
        unsigned int v = (lane < P1_THREADS / 32) ? warp_sums[lane] : 0u;
        #pragma unroll
        for (int off = 8; off > 0; off >>= 1)
            v += __shfl_down_sync(0xFFFFFFFFu, v, off);
        if (lane == 0 && v)
            atomicAdd(&g_sum, (unsigned long long)v);
    }
}

// ---------------------------------------------------------------- phase 2
__global__ void __launch_bounds__(P2_THREADS) phase2_kernel(
    const float* __restrict__ c_real,
    const float* __restrict__ c_imag)
{
    const unsigned int total  = g_nsurv;
    const unsigned int stride = gridDim.x * blockDim.x;

    unsigned int local = 0;

    for (unsigned int s = blockIdx.x * blockDim.x + threadIdx.x;
         s < total; s += stride) {
        const unsigned int idx = g_surv[s];
        const float cr = __ldg(c_real + idx);
        const float ci = __ldg(c_imag + idx);

        float zr = 0.0f, zi = 0.0f;
        int iters = MAX_ITERS;   // never escaped / cycled -> 100

        for (int i = 0; i < MAX_ITERS; ++i) {
            float zr2 = zr * zr - zi * zi + cr;            // same expr as R1
            float zi2 = fmaf(2.0f * zr, zi, ci);

            // cycle detection (skipped at i==0); wins over escape same-step
            if (i > 0) {
                float dr = fabsf(zr2 - zr);
                float di = fabsf(zi2 - zi);
                if (dr < 1e-6f && di < 1e-6f) { iters = MAX_ITERS; break; }
            }

            if (fmaf(zr2, zr2, zi2 * zi2) > 4.0f) { iters = i + 1; break; }

            zr = zr2; zi = zi2;
        }

        local += (unsigned int)abs(iters - 30);
    }

    // ---- reduction ----
    #pragma unroll
    for (int off = 16; off > 0; off >>= 1)
        local += __shfl_down_sync(0xFFFFFFFFu, local, off);

    __shared__ unsigned int warp_sums[P2_THREADS / 32];
    const int lane = threadIdx.x & 31;
    const int wid  = threadIdx.x >> 5;
    if (lane == 0) warp_sums[wid] = local;
    __syncthreads();

    if (wid == 0) {
        unsigned int v = (lane < P2_THREADS / 32) ? warp_sums[lane] : 0u;
        #pragma unroll
        for (int off = 4; off > 0; off >>= 1)
            v += __shfl_down_sync(0xFFFFFFFFu, v, off);
        if (lane == 0 && v)
            atomicAdd(&g_sum, (unsigned long long)v);
    }
}

// ---------------------------------------------------------------- finalize
__global__ void finalize_kernel(float* __restrict__ out, int n)
{
    double s = (double)g_sum;
    out[0] = (float)(s * (0.1 / 30.0) / (double)n);
    // reset for next graph replay (identical state each call => deterministic)
    g_sum = 0ULL;
    g_nsurv = 0u;
}

extern "C" void kernel_launch(void* const* d_in, const int* in_sizes, int n_in,
                              void* d_out, int out_size)
{
    const float* c_real = (const float*)d_in[0];
    const float* c_imag = (const float*)d_in[1];
    float* out = (float*)d_out;
    const int n = in_sizes[0];

    const int p1_blocks = (n + P1_THREADS - 1) / P1_THREADS;
    phase1_kernel<<<p1_blocks, P1_THREADS>>>(c_real, c_imag, n);

    phase2_kernel<<<P2_BLOCKS, P2_THREADS>>>(c_real, c_imag);

    finalize_kernel<<<1, 1>>>(out, n);
}

// round 5
// speedup vs baseline: 1.1655x; 1.1655x over previous
#include <cuda_runtime.h>

// Mandelbrot boundary-proximity loss.
// R5: phase 1 = 4 points/thread (float4 loads, amortized epilogue), K1=8,
// branchless iteration; phase 2 = exact replay of survivors (unchanged,
// bit-identical to validated R1 arithmetic, so moving the K1 boundary
// cannot change the result).
//
// Reduction: exact integer sum (ULL atomics) => deterministic.

#define MAX_ITERS 100
#define K1 8
#define NMAX 8388608
#define P1_THREADS 256
#define P1_PTS 4
#define P2_BLOCKS 2048
#define P2_THREADS 256

__device__ unsigned long long g_sum;      // zero-init at load
__device__ unsigned int g_nsurv;          // zero-init at load
__device__ unsigned int g_surv[NMAX];

// ---------------------------------------------------------------- phase 1
__global__ void __launch_bounds__(P1_THREADS) phase1_kernel(
    const float* __restrict__ c_real,
    const float* __restrict__ c_imag,
    int n)
{
    const int tid  = blockIdx.x * P1_THREADS + threadIdx.x;
    const int base = tid * P1_PTS;
    const int lane = threadIdx.x & 31;
    const int wid  = threadIdx.x >> 5;

    float cr[P1_PTS], ci[P1_PTS];
    bool valid[P1_PTS];

    if (base + P1_PTS - 1 < n) {
        const float4 r4 = *reinterpret_cast<const float4*>(c_real + base);
        const float4 i4 = *reinterpret_cast<const float4*>(c_imag + base);
        cr[0] = r4.x; cr[1] = r4.y; cr[2] = r4.z; cr[3] = r4.w;
        ci[0] = i4.x; ci[1] = i4.y; ci[2] = i4.z; ci[3] = i4.w;
        #pragma unroll
        for (int p = 0; p < P1_PTS; ++p) valid[p] = true;
    } else {
        #pragma unroll
        for (int p = 0; p < P1_PTS; ++p) {
            valid[p] = (base + p) < n;
            cr[p] = valid[p] ? c_real[base + p] : 10.0f;  // dummy: escapes fast
            ci[p] = valid[p] ? c_imag[base + p] : 0.0f;
        }
    }

    // per-point state
    bool in_set[P1_PTS], esc[P1_PTS];
    int cnt[P1_PTS];
    float zr[P1_PTS], zi[P1_PTS];

    #pragma unroll
    for (int p = 0; p < P1_PTS; ++p) {
        // analytic in-set tests (main cardioid + period-2 bulb)
        const float c2 = ci[p] * ci[p];
        const float xm = cr[p] - 0.25f;
        const float q  = xm * xm + c2;
        const float xp = cr[p] + 1.0f;
        in_set[p] = (q * (q + xm) < 0.25f * c2) | (xp * xp + c2 < 0.0625f);
        esc[p] = false;
        cnt[p] = 0;
        zr[p] = 0.0f;
        zi[p] = 0.0f;
    }

    // branchless 8-step escape probe, 4 independent chains (ILP)
    #pragma unroll
    for (int i = 0; i < K1; ++i) {
        #pragma unroll
        for (int p = 0; p < P1_PTS; ++p) {
            float zr2 = zr[p] * zr[p] - zi[p] * zi[p] + cr[p]; // same as R1
            float zi2 = fmaf(2.0f * zr[p], zi[p], ci[p]);
            float mag = fmaf(zr2, zr2, zi2 * zi2);
            esc[p] |= (mag > 4.0f);            // sticky: NaN-safe post-escape
            cnt[p] += esc[p] ? 0 : 1;
            zr[p] = zr2; zi[p] = zi2;
        }
    }

    // classify: dist and survivor mask
    unsigned int dist = 0;
    unsigned int smask = 0;                    // bit p = point p survives
    #pragma unroll
    for (int p = 0; p < P1_PTS; ++p) {
        if (valid[p]) {
            if (in_set[p])      dist += 70u;           // iters = 100 exactly
            else if (esc[p])    dist += (unsigned int)(29 - cnt[p]);
            else                smask |= (1u << p);
        }
    }

    // ---- survivor append: warp shfl-scan of per-thread counts ----
    const int k = __popc(smask);
    int incl = k;
    #pragma unroll
    for (int off = 1; off < 32; off <<= 1) {
        int v = __shfl_up_sync(0xFFFFFFFFu, incl, off);
        if (lane >= off) incl += v;
    }
    const int excl = incl - k;
    const int warp_total = __shfl_sync(0xFFFFFFFFu, incl, 31);

    __shared__ unsigned int warp_base[P1_THREADS / 32];
    __shared__ unsigned int block_base;
    if (lane == 0) warp_base[wid] = (unsigned int)warp_total;
    __syncthreads();
    if (threadIdx.x == 0) {
        unsigned int tot = 0;
        #pragma unroll
        for (int w = 0; w < P1_THREADS / 32; ++w) {
            unsigned int c = warp_base[w];
            warp_base[w] = tot;
            tot += c;
        }
        block_base = tot ? atomicAdd(&g_nsurv, tot) : 0u;
    }
    __syncthreads();

    if (smask) {
        unsigned int pos = block_base + warp_base[wid] + (unsigned int)excl;
        #pragma unroll
        for (int p = 0; p < P1_PTS; ++p)
            if (smask & (1u << p))
                g_surv[pos++] = (unsigned int)(base + p);
    }

    // ---- exact-integer distance reduction ----
    #pragma unroll
    for (int off = 16; off > 0; off >>= 1)
        dist += __shfl_down_sync(0xFFFFFFFFu, dist, off);

    __shared__ unsigned int warp_sums[P1_THREADS / 32];
    if (lane == 0) warp_sums[wid] = dist;
    __syncthreads();

    if (wid == 0) {
        unsigned int v = (lane < P1_THREADS / 32) ? warp_sums[lane] : 0u;
        #pragma unroll
        for (int off = 4; off > 0; off >>= 1)
            v += __shfl_down_sync(0xFFFFFFFFu, v, off);
        if (lane == 0 && v)
            atomicAdd(&g_sum, (unsigned long long)v);
    }
}

// ---------------------------------------------------------------- phase 2
__global__ void __launch_bounds__(P2_THREADS) phase2_kernel(
    const float* __restrict__ c_real,
    const float* __restrict__ c_imag)
{
    const unsigned int total  = g_nsurv;
    const unsigned int stride = gridDim.x * blockDim.x;

    unsigned int local = 0;

    for (unsigned int s = blockIdx.x * blockDim.x + threadIdx.x;
         s < total; s += stride) {
        const unsigned int idx = g_surv[s];
        const float cr = __ldg(c_real + idx);
        const float ci = __ldg(c_imag + idx);

        float zr = 0.0f, zi = 0.0f;
        int iters = MAX_ITERS;   // never escaped / cycled -> 100

        for (int i = 0; i < MAX_ITERS; ++i) {
            float zr2 = zr * zr - zi * zi + cr;            // same expr as R1
            float zi2 = fmaf(2.0f * zr, zi, ci);

            // cycle detection (skipped at i==0); wins over escape same-step
            if (i > 0) {
                float dr = fabsf(zr2 - zr);
                float di = fabsf(zi2 - zi);
                if (dr < 1e-6f && di < 1e-6f) { iters = MAX_ITERS; break; }
            }

            if (fmaf(zr2, zr2, zi2 * zi2) > 4.0f) { iters = i + 1; break; }

            zr = zr2; zi = zi2;
        }

        local += (unsigned int)abs(iters - 30);
    }

    // ---- reduction ----
    #pragma unroll
    for (int off = 16; off > 0; off >>= 1)
        local += __shfl_down_sync(0xFFFFFFFFu, local, off);

    __shared__ unsigned int warp_sums[P2_THREADS / 32];
    const int lane = threadIdx.x & 31;
    const int wid  = threadIdx.x >> 5;
    if (lane == 0) warp_sums[wid] = local;
    __syncthreads();

    if (wid == 0) {
        unsigned int v = (lane < P2_THREADS / 32) ? warp_sums[lane] : 0u;
        #pragma unroll
        for (int off = 4; off > 0; off >>= 1)
            v += __shfl_down_sync(0xFFFFFFFFu, v, off);
        if (lane == 0 && v)
            atomicAdd(&g_sum, (unsigned long long)v);
    }
}

// ---------------------------------------------------------------- finalize
__global__ void finalize_kernel(float* __restrict__ out, int n)
{
    double s = (double)g_sum;
    out[0] = (float)(s * (0.1 / 30.0) / (double)n);
    // reset for next graph replay (identical state each call => deterministic)
    g_sum = 0ULL;
    g_nsurv = 0u;
}

extern "C" void kernel_launch(void* const* d_in, const int* in_sizes, int n_in,
                              void* d_out, int out_size)
{
    const float* c_real = (const float*)d_in[0];
    const float* c_imag = (const float*)d_in[1];
    float* out = (float*)d_out;
    const int n = in_sizes[0];

    const int pts_per_block = P1_THREADS * P1_PTS;
    const int p1_blocks = (n + pts_per_block - 1) / pts_per_block;
    phase1_kernel<<<p1_blocks, P1_THREADS>>>(c_real, c_imag, n);

    phase2_kernel<<<P2_BLOCKS, P2_THREADS>>>(c_real, c_imag);

    finalize_kernel<<<1, 1>>>(out, n);
}

// round 6
// speedup vs baseline: 1.3473x; 1.1560x over previous
#include <cuda_runtime.h>

// Mandelbrot boundary-proximity loss. R6:
//  - phase 1: 4 pts/thread, K1=12, branchless, float predicated counter
//  - phase 2: branchless 100-iter replay, NO cycle check (cycle detection is
//    value-neutral: in_cycle => iters=100 == exhaustion result; divergence
//    only for measure~0 near-repelling-fixed-point passes), chunk-4 with
//    __all_sync early exit, finalize fused via last-block-done ticket.
//  - exact integer reduction (ULL atomics) => deterministic.

#define MAX_ITERS 100
#define K1 12
#define NMAX 8388608
#define P1_THREADS 256
#define P1_PTS 4
#define P2_BLOCKS 4096
#define P2_THREADS 256

__device__ unsigned long long g_sum;   // zero-init at load
__device__ unsigned int g_nsurv;       // zero-init at load
__device__ unsigned int g_done;        // zero-init at load
__device__ unsigned int g_surv[NMAX];

// ---------------------------------------------------------------- phase 1
__global__ void __launch_bounds__(P1_THREADS) phase1_kernel(
    const float* __restrict__ c_real,
    const float* __restrict__ c_imag,
    int n)
{
    const int tid  = blockIdx.x * P1_THREADS + threadIdx.x;
    const int base = tid * P1_PTS;
    const int lane = threadIdx.x & 31;
    const int wid  = threadIdx.x >> 5;

    float cr[P1_PTS], ci[P1_PTS];
    bool valid[P1_PTS];

    if (base + P1_PTS - 1 < n) {
        const float4 r4 = *reinterpret_cast<const float4*>(c_real + base);
        const float4 i4 = *reinterpret_cast<const float4*>(c_imag + base);
        cr[0] = r4.x; cr[1] = r4.y; cr[2] = r4.z; cr[3] = r4.w;
        ci[0] = i4.x; ci[1] = i4.y; ci[2] = i4.z; ci[3] = i4.w;
        #pragma unroll
        for (int p = 0; p < P1_PTS; ++p) valid[p] = true;
    } else {
        #pragma unroll
        for (int p = 0; p < P1_PTS; ++p) {
            valid[p] = (base + p) < n;
            cr[p] = valid[p] ? c_real[base + p] : 10.0f;  // dummy escapes fast
            ci[p] = valid[p] ? c_imag[base + p] : 0.0f;
        }
    }

    bool in_set[P1_PTS], esc[P1_PTS];
    float cnt[P1_PTS], zr[P1_PTS], zi[P1_PTS];

    #pragma unroll
    for (int p = 0; p < P1_PTS; ++p) {
        // analytic in-set tests (main cardioid + period-2 bulb)
        const float c2 = ci[p] * ci[p];
        const float xm = cr[p] - 0.25f;
        const float q  = xm * xm + c2;
        const float xp = cr[p] + 1.0f;
        in_set[p] = (q * (q + xm) < 0.25f * c2) | (xp * xp + c2 < 0.0625f);
        esc[p] = false; cnt[p] = 0.0f; zr[p] = 0.0f; zi[p] = 0.0f;
    }

    #pragma unroll
    for (int i = 0; i < K1; ++i) {
        #pragma unroll
        for (int p = 0; p < P1_PTS; ++p) {
            float zr2 = zr[p] * zr[p] - zi[p] * zi[p] + cr[p]; // same as R1
            float zi2 = fmaf(2.0f * zr[p], zi[p], ci[p]);
            float mag = fmaf(zr2, zr2, zi2 * zi2);
            esc[p] |= (mag > 4.0f);          // sticky: NaN-safe post-escape
            if (!esc[p]) cnt[p] += 1.0f;     // predicated FADD (fma pipe)
            zr[p] = zr2; zi[p] = zi2;
        }
    }

    unsigned int dist = 0;
    unsigned int smask = 0;
    #pragma unroll
    for (int p = 0; p < P1_PTS; ++p) {
        if (valid[p]) {
            if (in_set[p])   dist += 70u;                      // iters = 100
            else if (esc[p]) dist += (unsigned int)(29.0f - cnt[p]);
            else             smask |= (1u << p);
        }
    }

    // ---- survivor append: warp shfl-scan of per-thread counts ----
    const int k = __popc(smask);
    int incl = k;
    #pragma unroll
    for (int off = 1; off < 32; off <<= 1) {
        int v = __shfl_up_sync(0xFFFFFFFFu, incl, off);
        if (lane >= off) incl += v;
    }
    const int excl = incl - k;
    const int warp_total = __shfl_sync(0xFFFFFFFFu, incl, 31);

    __shared__ unsigned int warp_base[P1_THREADS / 32];
    __shared__ unsigned int block_base;
    if (lane == 0) warp_base[wid] = (unsigned int)warp_total;
    __syncthreads();
    if (threadIdx.x == 0) {
        unsigned int tot = 0;
        #pragma unroll
        for (int w = 0; w < P1_THREADS / 32; ++w) {
            unsigned int c = warp_base[w];
            warp_base[w] = tot;
            tot += c;
        }
        block_base = tot ? atomicAdd(&g_nsurv, tot) : 0u;
    }
    __syncthreads();

    if (smask) {
        unsigned int pos = block_base + warp_base[wid] + (unsigned int)excl;
        #pragma unroll
        for (int p = 0; p < P1_PTS; ++p)
            if (smask & (1u << p))
                g_surv[pos++] = (unsigned int)(base + p);
    }

    // ---- exact-integer distance reduction ----
    #pragma unroll
    for (int off = 16; off > 0; off >>= 1)
        dist += __shfl_down_sync(0xFFFFFFFFu, dist, off);

    __shared__ unsigned int warp_sums[P1_THREADS / 32];
    if (lane == 0) warp_sums[wid] = dist;
    __syncthreads();

    if (wid == 0) {
        unsigned int v = (lane < P1_THREADS / 32) ? warp_sums[lane] : 0u;
        #pragma unroll
        for (int off = 4; off > 0; off >>= 1)
            v += __shfl_down_sync(0xFFFFFFFFu, v, off);
        if (lane == 0 && v)
            atomicAdd(&g_sum, (unsigned long long)v);
    }
}

// ------------------------------------------------- phase 2 (+ finalize)
__global__ void __launch_bounds__(P2_THREADS) phase2_kernel(
    const float* __restrict__ c_real,
    const float* __restrict__ c_imag,
    float* __restrict__ out,
    int n)
{
    const unsigned int total  = g_nsurv;
    const unsigned int stride = gridDim.x * blockDim.x;
    const int lane = threadIdx.x & 31;
    const int wid  = threadIdx.x >> 5;

    unsigned int local = 0;

    for (unsigned int s = blockIdx.x * blockDim.x + threadIdx.x;
         __any_sync(0xFFFFFFFFu, s < total); s += stride) {
        const bool has = (s < total);
        const unsigned int idx = has ? g_surv[s] : 0u;
        const float cr = has ? __ldg(c_real + idx) : 10.0f;  // dummy escapes
        const float ci = has ? __ldg(c_imag + idx) : 0.0f;

        float zr = 0.0f, zi = 0.0f, cnt = 0.0f;
        bool esc = false;

        #pragma unroll 1
        for (int chunk = 0; chunk < MAX_ITERS / 4; ++chunk) {
            #pragma unroll
            for (int j = 0; j < 4; ++j) {
                float zr2 = zr * zr - zi * zi + cr;        // same expr as R1
                float zi2 = fmaf(2.0f * zr, zi, ci);
                float mag = fmaf(zr2, zr2, zi2 * zi2);
                esc |= (mag > 4.0f);        // sticky; NaN-safe post-escape
                if (!esc) cnt += 1.0f;      // predicated FADD
                zr = zr2; zi = zi2;
            }
            if (__all_sync(0xFFFFFFFFu, esc)) break;
        }

        if (has) {
            // iters = esc ? cnt+1 : 100 ; dist = |iters-30|
            unsigned int d = esc ? (unsigned int)fabsf(cnt - 29.0f) : 70u;
            local += d;
        }
    }

    // ---- reduction ----
    #pragma unroll
    for (int off = 16; off > 0; off >>= 1)
        local += __shfl_down_sync(0xFFFFFFFFu, local, off);

    __shared__ unsigned int warp_sums[P2_THREADS / 32];
    if (lane == 0) warp_sums[wid] = local;
    __syncthreads();

    if (wid == 0) {
        unsigned int v = (lane < P2_THREADS / 32) ? warp_sums[lane] : 0u;
        #pragma unroll
        for (int off = 4; off > 0; off >>= 1)
            v += __shfl_down_sync(0xFFFFFFFFu, v, off);
        if (lane == 0 && v)
            atomicAdd(&g_sum, (unsigned long long)v);
    }

    // ---- last-block finalize (threadFenceReduction pattern) ----
    if (threadIdx.x == 0) {
        __threadfence();
        unsigned int ticket = atomicAdd(&g_done, 1u);
        if (ticket == gridDim.x - 1u) {
            __threadfence();
            double s = (double)g_sum;
            out[0] = (float)(s * (0.1 / 30.0) / (double)n);
            // reset for next graph replay (identical state each call)
            g_sum = 0ULL;
            g_nsurv = 0u;
            g_done = 0u;
        }
    }
}

extern "C" void kernel_launch(void* const* d_in, const int* in_sizes, int n_in,
                              void* d_out, int out_size)
{
    const float* c_real = (const float*)d_in[0];
    const float* c_imag = (const float*)d_in[1];
    float* out = (float*)d_out;
    const int n = in_sizes[0];

    const int pts_per_block = P1_THREADS * P1_PTS;
    const int p1_blocks = (n + pts_per_block - 1) / pts_per_block;
    phase1_kernel<<<p1_blocks, P1_THREADS>>>(c_real, c_imag, n);

    phase2_kernel<<<P2_BLOCKS, P2_THREADS>>>(c_real, c_imag, out, n);
}